// round 11
// baseline (speedup 1.0000x reference)
#include <cuda_runtime.h>
#include <cstdint>

// ---------------------------------------------------------------- dims
#define T_STEPS 32
#define B_DIM   256
#define F_DIM   2048
#define H_DIM   4096
#define M_DIM   (T_STEPS * B_DIM)   // 8192
#define K_DIM   F_DIM               // 2048
#define N_DIM   H_DIM               // 4096
#define BH      (B_DIM * H_DIM)     // 1048576

// ---------------------------------------------------------------- fused GEMM + LIF
// cp.async edition: smem holds gmem-native K-major tiles (row stride 20
// floats), 3-stage cp.async pipeline, no register staging / no STS.
// Inner loop fetches float4 fragments along k; the 4 scalar fmas per
// component keep k strictly ascending with a single accumulator ->
// bit-exact with reference (rel_err 0.0). LIF fused in epilogue.
#define BM   128
#define BN   128
#define BK   16
#define RSTR 20                            // floats per smem row (16 + pad 4)
#define A_F  (BM * RSTR)                   // 2560 floats
#define STAGE_F (2 * A_F)                  // 5120 floats (A then B)
#define STAGES  3
#define SMEM_DYN (STAGES * STAGE_F * 4)    // 61440 bytes
#define STR  132                           // epilogue Cs row stride

__device__ __forceinline__ uint32_t smem_u32(const void* p) {
    uint32_t a;
    asm("{ .reg .u64 t; cvta.to.shared.u64 t, %1; cvt.u32.u64 %0, t; }"
        : "=r"(a) : "l"(p));
    return a;
}

#define CP16(dst, src) \
    asm volatile("cp.async.cg.shared.global [%0], [%1], 16;" \
                 :: "r"(dst), "l"(src) : "memory")

__global__ __launch_bounds__(256, 2)
void gemm_lif_fused(const float* __restrict__ A,
                    const float* __restrict__ W,
                    const float* __restrict__ bias,
                    float* __restrict__ out)
{
    extern __shared__ __align__(16) float sm[];
    const uint32_t sb = smem_u32(sm);

    const int tid  = threadIdx.x;
    const int lane = tid & 31;
    const int wid  = tid >> 5;
    const int wm   = wid >> 2;            // 0..1 warp row (64 rows)
    const int wn   = wid & 3;             // 0..3 warp col (32 cols)
    const int lr   = lane >> 2;           // 0..7 lane row
    const int lc   = lane & 3;            // 0..3 lane col

    const int rowBase = blockIdx.y * BM;  // permuted row space
    const int colBase = blockIdx.x * BN;

    // loader indices: thread covers rows r0 and r1, k-chunk kq (4 floats)
    const int r0 = tid >> 2;              // 0..63
    const int r1 = r0 + 64;               // 64..127
    const int kq = (tid & 3) << 2;        // 0,4,8,12

    // permuted A rows: local r -> global row ((r'&31)*256 + (r'>>5))
    const int rp0 = rowBase + r0;
    const int rp1 = rowBase + r1;
    const float* ApA = A + (size_t)(((rp0 & 31) << 8) + (rp0 >> 5)) * K_DIM + kq;
    const float* ApB = A + (size_t)(((rp1 & 31) << 8) + (rp1 >> 5)) * K_DIM + kq;
    const float* WpA = W + (size_t)(colBase + r0) * K_DIM + kq;
    const float* WpB = W + (size_t)(colBase + r1) * K_DIM + kq;

    // smem byte destinations for this thread's 4 chunks (per stage)
    const uint32_t dA0 = sb + (uint32_t)(r0 * RSTR + kq) * 4;
    const uint32_t dA1 = sb + (uint32_t)(r1 * RSTR + kq) * 4;
    const uint32_t dB0 = sb + (uint32_t)(A_F + r0 * RSTR + kq) * 4;
    const uint32_t dB1 = sb + (uint32_t)(A_F + r1 * RSTR + kq) * 4;

    float acc[8][8];
#pragma unroll
    for (int i = 0; i < 8; i++)
#pragma unroll
        for (int j = 0; j < 8; j++) acc[i][j] = 0.0f;

    // fragment base offsets (floats)
    const int aBase = (wm * 64 + lr) * RSTR;      // + i*8*RSTR + g*4
    const int bBase = A_F + (wn * 32 + lc) * RSTR; // + j*4*RSTR + g*4

    const int NIT = K_DIM / BK;   // 128

    // prologue: stages 0 and 1
    {
        const uint32_t s0 = 0;
        CP16(dA0 + s0, ApA);  CP16(dA1 + s0, ApB);
        CP16(dB0 + s0, WpA);  CP16(dB1 + s0, WpB);
        asm volatile("cp.async.commit_group;" ::: "memory");
        const uint32_t s1 = STAGE_F * 4;
        CP16(dA0 + s1, ApA + BK);  CP16(dA1 + s1, ApB + BK);
        CP16(dB0 + s1, WpA + BK);  CP16(dB1 + s1, WpB + BK);
        asm volatile("cp.async.commit_group;" ::: "memory");
    }

    int st = 0;                    // stage index of iter it
    for (int it = 0; it < NIT; it++) {
        asm volatile("cp.async.wait_group 1;" ::: "memory");
        __syncthreads();

        // issue loads for it+2 into stage (st+2)%3
        if (it + 2 < NIT) {
            int s2 = st + 2; if (s2 >= STAGES) s2 -= STAGES;
            const uint32_t so = (uint32_t)(s2 * STAGE_F * 4);
            const size_t off = (size_t)(it + 2) * BK;
            CP16(dA0 + so, ApA + off);  CP16(dA1 + so, ApB + off);
            CP16(dB0 + so, WpA + off);  CP16(dB1 + so, WpB + off);
        }
        asm volatile("cp.async.commit_group;" ::: "memory");

        const float* Sb = sm + st * STAGE_F;
#pragma unroll
        for (int g = 0; g < 4; g++) {          // 4 k's per group
            float4 Af[8];
#pragma unroll
            for (int i = 0; i < 8; i++)
                Af[i] = *(const float4*)(Sb + aBase + i * 8 * RSTR + g * 4);
#pragma unroll
            for (int j = 0; j < 8; j++) {
                float4 Bf = *(const float4*)(Sb + bBase + j * 4 * RSTR + g * 4);
#pragma unroll
                for (int i = 0; i < 8; i++) {
                    acc[i][j] = fmaf(Af[i].x, Bf.x, acc[i][j]);
                    acc[i][j] = fmaf(Af[i].y, Bf.y, acc[i][j]);
                    acc[i][j] = fmaf(Af[i].z, Bf.z, acc[i][j]);
                    acc[i][j] = fmaf(Af[i].w, Bf.w, acc[i][j]);
                }
            }
        }

        if (++st >= STAGES) st -= STAGES;
    }

    asm volatile("cp.async.wait_group 0;" ::: "memory");
    __syncthreads();

    // ---------------- fused epilogue: bias + LIF scan -----------------------
    float bb[8];
#pragma unroll
    for (int j = 0; j < 8; j++)
        bb[j] = bias[colBase + wn * 32 + j * 4 + lc];

    float* Cs = sm;   // 64 x STR floats = 33792 B <= 61440 B

#pragma unroll 1
    for (int half = 0; half < 2; half++) {
        if (wm == half) {
#pragma unroll
            for (int i = 0; i < 8; i++) {
                const int rloc = i * 8 + lr;
#pragma unroll
                for (int j = 0; j < 8; j++)
                    Cs[rloc * STR + wn * 32 + j * 4 + lc] = acc[i][j] + bb[j];
            }
        }
        __syncthreads();

        // 256 threads: 2 b-chunks x 128 columns, one LIF scan each
        {
            const int blocal = tid >> 7;          // 0..1
            const int col    = tid & 127;         // 0..127
            const int bG     = blockIdx.y * 4 + half * 2 + blocal;
            float* ob = out + (size_t)bG * H_DIM + colBase + col;
            const float* cs = Cs + (blocal * 32) * STR + col;
            float v = 0.0f, cnt = 0.0f;
#pragma unroll
            for (int t = 0; t < T_STEPS; t++) {
                float x = cs[t * STR];
                v = __fadd_rn(v, __fmul_rn(__fsub_rn(x, v), 0.5f));
                bool fire = (v >= 1.0f);
                float s = fire ? 1.0f : 0.0f;
                ob[(size_t)t * BH] = s;
                cnt += s;
                v = fire ? 0.0f : v;
            }
            ob[(size_t)T_STEPS * BH] = cnt;       // count block after spk_seq
        }
        __syncthreads();
    }
}

// ---------------------------------------------------------------- launch
extern "C" void kernel_launch(void* const* d_in, const int* in_sizes, int n_in,
                              void* d_out, int out_size)
{
    const float* x_seq = (const float*)d_in[0];  // [T,B,F]
    const float* W     = (const float*)d_in[1];  // [H,F]
    const float* b     = (const float*)d_in[2];  // [H]
    float* out = (float*)d_out;

    cudaFuncSetAttribute(gemm_lif_fused,
                         cudaFuncAttributeMaxDynamicSharedMemorySize, SMEM_DYN);

    dim3 gg(N_DIM / BN, M_DIM / BM);   // (32, 64)
    gemm_lif_fused<<<gg, 256, SMEM_DYN>>>(x_seq, W, b, out);
}